// round 13
// baseline (speedup 1.0000x reference)
#include <cuda_runtime.h>
#include <cuda_fp16.h>
#include <cstdint>

#define HIDDEN 128
#define NCOEF  8
#define NPROTO 256
#define NMAX   131072
#define TILE_M 128
#define NCHUNK 36            // 4 silu chunks + 32 spline chunks (4 i-cols x 8 c each)
#define KDIM   1152
#define TAU    4e-4f
#define NTHR   512
#define XSS    132           // padded xs row stride (conflict-free: 132 % 32 = 4)

// ---------------- device scratch ----------------
__device__ uint32_t g_Wh1[NCHUNK * 2048];
__device__ uint32_t g_Wl1[NCHUNK * 2048];
__device__ uint32_t g_Wh2[NCHUNK * 2048];
__device__ uint32_t g_Wl2[NCHUNK * 2048];
__device__ float g_Wf1[KDIM * HIDDEN];     // fp32 combined, [k][o] (fixup)
__device__ float g_Wf2[KDIM * HIDDEN];
__device__ float g_h[(size_t)NMAX * HIDDEN];
__device__ float g_pn[NPROTO * HIDDEN];
__device__ float g_pnT[HIDDEN * NPROTO];
__device__ float g_gp[2];                  // g0, invh
__device__ int   g_cnt;
__device__ int   g_list[NMAX];

// ---------------- helpers ----------------
__device__ __forceinline__ uint32_t smem_u32p(const void* p) {
    uint32_t a;
    asm("{ .reg .u64 t; cvta.to.shared.u64 t, %1; cvt.u32.u64 %0, t; }" : "=r"(a) : "l"(p));
    return a;
}
__device__ __forceinline__ uint32_t h2_split2(float v0, float v1, uint32_t& lo_out) {
    __half2 hp = __float22half2_rn(make_float2(v0, v1));
    float2 hf = __half22float2(hp);
    __half2 lp = __float22half2_rn(make_float2(v0 - hf.x, v1 - hf.y));
    lo_out = *(uint32_t*)&lp;
    return *(uint32_t*)&hp;
}
__device__ __forceinline__ void mma16(float* c, const uint32_t* a, const uint32_t* b) {
    asm volatile(
        "mma.sync.aligned.m16n8k16.row.col.f32.f16.f16.f32 "
        "{%0,%1,%2,%3}, {%4,%5,%6,%7}, {%8,%9}, {%0,%1,%2,%3};"
        : "+f"(c[0]), "+f"(c[1]), "+f"(c[2]), "+f"(c[3])
        : "r"(a[0]), "r"(a[1]), "r"(a[2]), "r"(a[3]), "r"(b[0]), "r"(b[1]));
}
#define LDSM_X4(r, a)                                                         \
    asm volatile("ldmatrix.sync.aligned.m8n8.x4.shared.b16 {%0,%1,%2,%3}, [%4];" \
        : "=r"((r)[0]), "=r"((r)[1]), "=r"((r)[2]), "=r"((r)[3]) : "r"(a))

__device__ __forceinline__ float bspline_c(float xv, int c, float g0, float invh) {
    float t = (xv - g0) * invh;
    float fj = floorf(t);
    float u = t - fj;
    int d = (int)fj - c;
    float v;
    if (d == 0)      v = u * u * u * (1.0f / 6.0f);
    else if (d == 1) v = (1.0f + 3.0f * u + 3.0f * u * u - 3.0f * u * u * u) * (1.0f / 6.0f);
    else if (d == 2) { float w = 1.0f - u; v = (1.0f + 3.0f * w + 3.0f * w * w - 3.0f * w * w * w) * (1.0f / 6.0f); }
    else if (d == 3) { float w = 1.0f - u; v = w * w * w * (1.0f / 6.0f); }
    else             v = 0.0f;
    return v;
}

// ---------------- prep kernels ----------------
__global__ void prep_grid(const float* __restrict__ grid) {
    if (threadIdx.x == 0) {
        g_gp[0] = grid[0];
        g_gp[1] = 1.0f / (grid[1] - grid[0]);
    }
}

// k-layout:
//  silu:   kc = i>>5 (0..3), kp = (i&31)>>1, half-lane = i&1
//  spline: kc = 4 + (i>>2) (4..35), kp = (i&3)*4 + (c>>1), half-lane = c&1
__global__ void prep_weights(const float* __restrict__ base_w,
                             const float* __restrict__ spline_w,
                             const float* __restrict__ scaler,
                             uint32_t* __restrict__ Wh, uint32_t* __restrict__ Wl,
                             float* __restrict__ Wf) {
    int idx = blockIdx.x * blockDim.x + threadIdx.x;
    if (idx >= HIDDEN * 64) return;
    int o = idx >> 6, m = idx & 63;
    int i0 = 2 * m, i1 = 2 * m + 1;
    int iq = m >> 4, kp = m & 15;

    float w0 = base_w[o * HIDDEN + i0];
    float w1 = base_w[o * HIDDEN + i1];
    uint32_t lo, hi = h2_split2(w0, w1, lo);
    Wh[iq * 2048 + o * 16 + kp] = hi;
    Wl[iq * 2048 + o * 16 + kp] = lo;
    Wf[(size_t)i0 * HIDDEN + o] = w0;
    Wf[(size_t)i1 * HIDDEN + o] = w1;

    float sc0 = scaler[o * HIDDEN + i0];
    float sc1 = scaler[o * HIDDEN + i1];
    int kcS = 4 + (i0 >> 2);   // same chunk for i0 and i1 (i0 even)
#pragma unroll
    for (int cp = 0; cp < 4; cp++) {
        float s0 = spline_w[(o * HIDDEN + i0) * NCOEF + 2 * cp]     * sc0;
        float s1 = spline_w[(o * HIDDEN + i0) * NCOEF + 2 * cp + 1] * sc0;
        hi = h2_split2(s0, s1, lo);
        int kp0 = (i0 & 3) * 4 + cp;
        Wh[kcS * 2048 + o * 16 + kp0] = hi;
        Wl[kcS * 2048 + o * 16 + kp0] = lo;
        Wf[(size_t)(HIDDEN + 2 * cp * HIDDEN + i0) * HIDDEN + o]       = s0;
        Wf[(size_t)(HIDDEN + (2 * cp + 1) * HIDDEN + i0) * HIDDEN + o] = s1;
        float s2 = spline_w[(o * HIDDEN + i1) * NCOEF + 2 * cp]     * sc1;
        float s3 = spline_w[(o * HIDDEN + i1) * NCOEF + 2 * cp + 1] * sc1;
        hi = h2_split2(s2, s3, lo);
        int kp1 = (i1 & 3) * 4 + cp;
        Wh[kcS * 2048 + o * 16 + kp1] = hi;
        Wl[kcS * 2048 + o * 16 + kp1] = lo;
        Wf[(size_t)(HIDDEN + 2 * cp * HIDDEN + i1) * HIDDEN + o]       = s2;
        Wf[(size_t)(HIDDEN + (2 * cp + 1) * HIDDEN + i1) * HIDDEN + o] = s3;
    }
}

__global__ void prep_protos(const float* __restrict__ protos) {
    int w = (blockIdx.x * blockDim.x + threadIdx.x) >> 5;
    int lane = threadIdx.x & 31;
    if (w >= NPROTO) return;
    float ss = 0.f;
    for (int i = lane; i < HIDDEN; i += 32) {
        float v = protos[w * HIDDEN + i];
        ss += v * v;
    }
#pragma unroll
    for (int off = 16; off; off >>= 1) ss += __shfl_xor_sync(0xffffffffu, ss, off);
    float inv = 1.0f / fmaxf(sqrtf(ss), 1e-8f);
    for (int i = lane; i < HIDDEN; i += 32) {
        float v = protos[w * HIDDEN + i] * inv;
        g_pn[w * HIDDEN + i] = v;
        g_pnT[i * NPROTO + w] = v;
    }
}

__global__ void reset_cnt() { g_cnt = 0; }

// ---------------- fused KAN layer ----------------
#define U_SA  (TILE_M * XSS)             // 16896
#define U_SB  (U_SA + 10240)
#define SM_WORDS (U_SB + 10240)          // 37376 u32 = 149504 B

__global__ void __launch_bounds__(NTHR, 1)
kan_tc(const float* __restrict__ in,
       const uint32_t* __restrict__ Wh, const uint32_t* __restrict__ Wl,
       float* __restrict__ out) {
    extern __shared__ float sm[];
    float* xs = sm;
    uint32_t* u32b = (uint32_t*)sm;

    const int tid  = threadIdx.x;
    const int lane = tid & 31;
    const int wid  = tid >> 5;        // 0..15
    const int wr   = wid >> 2;        // 0..3  rows wr*32
    const int wc   = wid & 3;         // 0..3  cols wc*32

    const float g0 = g_gp[0], invh = g_gp[1];
    const int m0 = blockIdx.x * TILE_M;

    // ldmatrix per-lane address bases (byte offsets into dynamic smem)
    const uint32_t smb = smem_u32p(sm);
    // A x4: m0 rows+0 klo | m1 rows+8 klo | m2 rows+0 khi | m3 rows+8 khi
    const int arow  = wr * 32 + ((lane >> 3) & 1) * 8 + (lane & 7);
    const int akoff = ((lane >> 4) & 1) * 4;
    const uint32_t aAddr0 = smb + 4u * (U_SA + arow * 20 + akoff);
    // B x4: m0 cols+0 klo | m1 cols+0 khi | m2 cols+8 klo | m3 cols+8 khi
    const int bcol  = wc * 32 + ((lane >> 4) & 1) * 8 + (lane & 7);
    const int bkoff = ((lane >> 3) & 1) * 4;
    const uint32_t bAddr0 = smb + 4u * (U_SB + bcol * 20 + bkoff);

    {   // x tile load into padded rows (stride XSS)
        const float4* src = (const float4*)(in + (size_t)m0 * HIDDEN);
#pragma unroll
        for (int j = 0; j < 8; j++) {
            int f = tid + j * NTHR;          // float4 id: r*32 + c4
            int r = f >> 5, c4 = f & 31;
            *(float4*)(xs + r * XSS + c4 * 4) = src[f];
        }
    }
    __syncthreads();

    float acc[2][4][4];
#pragma unroll
    for (int a = 0; a < 2; a++)
#pragma unroll
        for (int b = 0; b < 4; b++)
#pragma unroll
            for (int c = 0; c < 4; c++) acc[a][b][c] = 0.f;

#define STAGE(kc_, bb_) do {                                                         \
        uint32_t* dBh = u32b + U_SB + (bb_) * 5120;                                  \
        uint32_t* dBl = dBh + 2560;                                                  \
        const uint2* sh = (const uint2*)(Wh + (kc_) * 2048);                         \
        const uint2* sl = (const uint2*)(Wl + (kc_) * 2048);                         \
        _Pragma("unroll")                                                            \
        for (int j = 0; j < 2; j++) {                                                \
            int f2 = tid + j * NTHR;                                                 \
            int n = f2 >> 3, kp2 = f2 & 7;                                           \
            ((uint2*)(dBh + n * 20))[kp2] = sh[f2];                                  \
            ((uint2*)(dBl + n * 20))[kp2] = sl[f2];                                  \
        }                                                                            \
        uint32_t* dAh = u32b + U_SA + (bb_) * 5120;                                  \
        uint32_t* dAl = dAh + 2560;                                                  \
        if ((kc_) < 4) {                                                             \
            int ibase = (kc_) * 32;                                                  \
            _Pragma("unroll")                                                        \
            for (int j = 0; j < 4; j++) {                                            \
                int p = tid + j * NTHR;                                              \
                int r = p >> 4, kp = p & 15;                                         \
                float2 xv = *(const float2*)(xs + r * XSS + ibase + 2 * kp);         \
                float v0 = xv.x / (1.0f + __expf(-xv.x));                            \
                float v1 = xv.y / (1.0f + __expf(-xv.y));                            \
                uint32_t lo2, hi2 = h2_split2(v0, v1, lo2);                          \
                dAh[r * 20 + kp] = hi2;                                              \
                dAl[r * 20 + kp] = lo2;                                              \
            }                                                                        \
        } else {                                                                     \
            int ibase = ((kc_) - 4) * 4;                                             \
            int r = tid >> 2, q = tid & 3;                                           \
            float xv = xs[r * XSS + ibase + q];                                      \
            float t  = (xv - g0) * invh;                                             \
            float fj = floorf(t);                                                    \
            float u  = t - fj;                                                       \
            int jc   = (int)fj;                                                      \
            float u2 = u * u, u3 = u2 * u;                                           \
            float wd0 = u3 * (1.0f / 6.0f);                                          \
            float wd1 = (1.0f + 3.0f * u + 3.0f * u2 - 3.0f * u3) * (1.0f / 6.0f);   \
            float wm = 1.0f - u;                                                     \
            float wm2 = wm * wm;                                                     \
            float wd2 = (1.0f + 3.0f * wm + 3.0f * wm2 - 3.0f * wm2 * wm) * (1.0f / 6.0f); \
            float wd3 = wm2 * wm * (1.0f / 6.0f);                                    \
            float val[8];                                                            \
            _Pragma("unroll")                                                        \
            for (int c = 0; c < 8; c++) {                                            \
                float v = 0.f;                                                       \
                v = (jc == c)     ? wd0 : v;                                         \
                v = (jc == c + 1) ? wd1 : v;                                         \
                v = (jc == c + 2) ? wd2 : v;                                         \
                v = (jc == c + 3) ? wd3 : v;                                         \
                val[c] = v;                                                          \
            }                                                                        \
            uint32_t h0, h1, h2, h3, l0, l1, l2, l3;                                 \
            h0 = h2_split2(val[0], val[1], l0);                                      \
            h1 = h2_split2(val[2], val[3], l1);                                      \
            h2 = h2_split2(val[4], val[5], l2);                                      \
            h3 = h2_split2(val[6], val[7], l3);                                      \
            *(uint4*)(dAh + r * 20 + q * 4) = make_uint4(h0, h1, h2, h3);            \
            *(uint4*)(dAl + r * 20 + q * 4) = make_uint4(l0, l1, l2, l3);            \
        }                                                                            \
    } while (0)

    STAGE(0, 0);
    __syncthreads();

    for (int kc = 0; kc < NCHUNK; kc++) {
        const int b = kc & 1;
        if (kc < NCHUNK - 1) STAGE(kc + 1, b ^ 1);

        const uint32_t aB = aAddr0 + (uint32_t)b * 20480u;   // b*5120 u32
        const uint32_t bB = bAddr0 + (uint32_t)b * 20480u;

#pragma unroll
        for (int ks = 0; ks < 2; ks++) {
            const uint32_t kso = (uint32_t)ks * 32u;         // ks*8 u32
            uint32_t bh[8], bl[8];
            LDSM_X4(bh + 0, bB + kso);                        // nf0, nf1 (hi)
            LDSM_X4(bh + 4, bB + 1280u + kso);                // nf2, nf3 (hi)
            LDSM_X4(bl + 0, bB + 10240u + kso);               // nf0, nf1 (lo)
            LDSM_X4(bl + 4, bB + 10240u + 1280u + kso);       // nf2, nf3 (lo)
#pragma unroll
            for (int mf = 0; mf < 2; mf++) {
                uint32_t ah[4], al[4];
                LDSM_X4(ah, aB + (uint32_t)mf * 1280u + kso);
                LDSM_X4(al, aB + 10240u + (uint32_t)mf * 1280u + kso);
#pragma unroll
                for (int nf = 0; nf < 4; nf++) {
                    mma16(acc[mf][nf], ah, bh + nf * 2);
                    mma16(acc[mf][nf], ah, bl + nf * 2);
                    mma16(acc[mf][nf], al, bh + nf * 2);
                }
            }
        }
        __syncthreads();
    }

#pragma unroll
    for (int mf = 0; mf < 2; mf++) {
        int row = m0 + wr * 32 + mf * 16 + (lane >> 2);
#pragma unroll
        for (int nf = 0; nf < 4; nf++) {
            int col = wc * 32 + nf * 8 + (lane & 3) * 2;
            *(float2*)(out + (size_t)row * HIDDEN + col) =
                make_float2(acc[mf][nf][0], acc[mf][nf][1]);
            *(float2*)(out + (size_t)(row + 8) * HIDDEN + col) =
                make_float2(acc[mf][nf][2], acc[mf][nf][3]);
        }
    }
}

// ---------------- cluster: register-tiled fp32 GEMM + top-2 argmax ----------------
__global__ void __launch_bounds__(256, 1)
cluster_kernel(const float* __restrict__ emb, float* __restrict__ assignOut) {
    extern __shared__ float sm[];
    float* sR = sm;                  // 128*129
    float* sP = sm + 128 * 129;      // 64*129

    const int tid = threadIdx.x;
    const int rg  = tid >> 3;        // 0..31
    const int pg  = tid & 7;         // 0..7
    const int base = blockIdx.x * 128;

    for (int l = tid; l < 128 * HIDDEN; l += 256) {
        int r = l >> 7, i = l & 127;
        sR[r * 129 + i] = emb[(size_t)(base + r) * HIDDEN + i];
    }

    float t1[4], t2[4];
    int   i1[4];
#pragma unroll
    for (int j = 0; j < 4; j++) { t1[j] = -3.4e38f; t2[j] = -3.4e38f; i1[j] = 0; }

    for (int pq = 0; pq < 4; pq++) {
        __syncthreads();
        for (int l = tid; l < 64 * HIDDEN; l += 256) {
            int p = l >> 7, i = l & 127;
            sP[p * 129 + i] = g_pn[(size_t)(pq * 64 + p) * HIDDEN + i];
        }
        __syncthreads();

        float acc[4][8];
#pragma unroll
        for (int j = 0; j < 4; j++)
#pragma unroll
            for (int jj = 0; jj < 8; jj++) acc[j][jj] = 0.f;

        const float* rbase = sR + (rg * 4) * 129;
        const float* pbase = sP + pg * 129;
#pragma unroll 4
        for (int k = 0; k < HIDDEN; k++) {
            float rv0 = rbase[k];
            float rv1 = rbase[129 + k];
            float rv2 = rbase[258 + k];
            float rv3 = rbase[387 + k];
#pragma unroll
            for (int jj = 0; jj < 8; jj++) {
                float pv = pbase[jj * 8 * 129 + k];
                acc[0][jj] += rv0 * pv;
                acc[1][jj] += rv1 * pv;
                acc[2][jj] += rv2 * pv;
                acc[3][jj] += rv3 * pv;
            }
        }

#pragma unroll
        for (int j = 0; j < 4; j++) {
#pragma unroll
            for (int jj = 0; jj < 8; jj++) {
                float v = acc[j][jj];
                int idx = pq * 64 + jj * 8 + pg;
                if (v > t1[j]) { t2[j] = t1[j]; t1[j] = v; i1[j] = idx; }
                else if (v > t2[j]) { t2[j] = v; }
            }
        }
    }

#pragma unroll
    for (int j = 0; j < 4; j++) {
        float a1 = t1[j], a2 = t2[j];
        int   ai = i1[j];
#pragma unroll
        for (int off = 4; off; off >>= 1) {
            float b1 = __shfl_down_sync(0xffffffffu, a1, off, 8);
            float b2 = __shfl_down_sync(0xffffffffu, a2, off, 8);
            int   bi = __shfl_down_sync(0xffffffffu, ai, off, 8);
            if (b1 > a1 || (b1 == a1 && bi < ai)) {
                a2 = fmaxf(a1, b2); a1 = b1; ai = bi;
            } else {
                a2 = fmaxf(a2, b1);
            }
        }
        t1[j] = a1; t2[j] = a2; i1[j] = ai;
    }

    if (pg == 0) {
#pragma unroll
        for (int j = 0; j < 4; j++) {
            int row = base + rg * 4 + j;
            assignOut[row] = (float)i1[j];
            if (t1[j] - t2[j] < TAU) {
                int s = atomicAdd(&g_cnt, 1);
                g_list[s] = row;
            }
        }
    }
}

// ---------------- fp32 fixup ----------------
__global__ void __launch_bounds__(256, 1)
fixup_kernel(const float* __restrict__ x,
             const float* __restrict__ Wf1, const float* __restrict__ Wf2,
             float* __restrict__ assignOut) {
    extern __shared__ float sm[];
    float* A  = sm;                 // 36864
    float* hb = sm + 36864;         // 4096
    float* ws = sm + 40960;         // 4096
    __shared__ int ridx[32];
    __shared__ float rv[8];
    __shared__ int   rp[8];

    const int tid = threadIdx.x;
    const int start = blockIdx.x * 32;
    const int cnt = g_cnt;
    if (start >= cnt) return;
    const int nr = min(32, cnt - start);
    if (tid < 32) {
        int srci = start + (tid < nr ? tid : nr - 1);
        ridx[tid] = g_list[srci];
    }
    __syncthreads();

    const float g0 = g_gp[0], invh = g_gp[1];
    const int tr = tid >> 5;
    const int tc = tid & 31;

    float acc[4][4];
    const float* Wf = Wf1;
    const float* src = x;
    bool gather = true;

    for (int layer = 0; layer < 2; layer++) {
        for (int e = tid; e < 32 * HIDDEN; e += 256) {
            int r = e >> 7, i = e & 127;
            float xv = gather ? src[(size_t)ridx[r] * HIDDEN + i] : src[r * HIDDEN + i];
            A[r * KDIM + i] = xv / (1.0f + __expf(-xv));
#pragma unroll
            for (int c = 0; c < NCOEF; c++)
                A[r * KDIM + HIDDEN + c * HIDDEN + i] = bspline_c(xv, c, g0, invh);
        }

#pragma unroll
        for (int a = 0; a < 4; a++)
#pragma unroll
            for (int b = 0; b < 4; b++) acc[a][b] = 0.f;

        for (int k0 = 0; k0 < KDIM; k0 += 32) {
            __syncthreads();
            const float4* gw = (const float4*)(Wf + (size_t)k0 * HIDDEN);
#pragma unroll
            for (int l = 0; l < 4; l++)
                ((float4*)ws)[tid + l * 256] = gw[tid + l * 256];
            __syncthreads();
#pragma unroll
            for (int kk = 0; kk < 32; kk++) {
                float a0 = A[(tr * 4 + 0) * KDIM + k0 + kk];
                float a1 = A[(tr * 4 + 1) * KDIM + k0 + kk];
                float a2 = A[(tr * 4 + 2) * KDIM + k0 + kk];
                float a3 = A[(tr * 4 + 3) * KDIM + k0 + kk];
                float4 w = ((float4*)ws)[kk * 32 + tc];
                acc[0][0] += a0 * w.x; acc[0][1] += a0 * w.y; acc[0][2] += a0 * w.z; acc[0][3] += a0 * w.w;
                acc[1][0] += a1 * w.x; acc[1][1] += a1 * w.y; acc[1][2] += a1 * w.z; acc[1][3] += a1 * w.w;
                acc[2][0] += a2 * w.x; acc[2][1] += a2 * w.y; acc[2][2] += a2 * w.z; acc[2][3] += a2 * w.w;
                acc[3][0] += a3 * w.x; acc[3][1] += a3 * w.y; acc[3][2] += a3 * w.z; acc[3][3] += a3 * w.w;
            }
        }
        __syncthreads();
#pragma unroll
        for (int ri = 0; ri < 4; ri++)
            ((float4*)(hb + (tr * 4 + ri) * HIDDEN))[tc] =
                make_float4(acc[ri][0], acc[ri][1], acc[ri][2], acc[ri][3]);
        __syncthreads();

        Wf = Wf2; src = hb; gather = false;
    }

    float sims[32];
#pragma unroll
    for (int r = 0; r < 32; r++) sims[r] = 0.f;
    for (int i = 0; i < HIDDEN; i++) {
        float pv = g_pnT[i * NPROTO + tid];
#pragma unroll
        for (int r = 0; r < 32; r++) sims[r] += hb[r * HIDDEN + i] * pv;
    }

    for (int r = 0; r < 32; r++) {
        float v = sims[r]; int bi = tid;
#pragma unroll
        for (int off = 16; off; off >>= 1) {
            float ov = __shfl_down_sync(0xffffffffu, v, off);
            int   oi = __shfl_down_sync(0xffffffffu, bi, off);
            if (ov > v || (ov == v && oi < bi)) { v = ov; bi = oi; }
        }
        if ((tid & 31) == 0) { rv[tid >> 5] = v; rp[tid >> 5] = bi; }
        __syncthreads();
        if (tid == 0) {
            float bv = rv[0]; int bb = rp[0];
#pragma unroll
            for (int w = 1; w < 8; w++)
                if (rv[w] > bv || (rv[w] == bv && rp[w] < bb)) { bv = rv[w]; bb = rp[w]; }
            if (r < nr) assignOut[ridx[r]] = (float)bb;
        }
        __syncthreads();
    }
}

// ---------------- launch ----------------
extern "C" void kernel_launch(void* const* d_in, const int* in_sizes, int n_in,
                              void* d_out, int out_size) {
    const float* x         = (const float*)d_in[0];
    const float* protos    = (const float*)d_in[1];
    const float* grid      = (const float*)d_in[2];
    const float* base_w1   = (const float*)d_in[3];
    const float* spline_w1 = (const float*)d_in[4];
    const float* scaler1   = (const float*)d_in[5];
    const float* base_w2   = (const float*)d_in[6];
    const float* spline_w2 = (const float*)d_in[7];
    const float* scaler2   = (const float*)d_in[8];

    int n = in_sizes[0] / HIDDEN;

    uint32_t *Wh1, *Wl1, *Wh2, *Wl2;
    float *Wf1, *Wf2, *h;
    cudaGetSymbolAddress((void**)&Wh1, g_Wh1);
    cudaGetSymbolAddress((void**)&Wl1, g_Wl1);
    cudaGetSymbolAddress((void**)&Wh2, g_Wh2);
    cudaGetSymbolAddress((void**)&Wl2, g_Wl2);
    cudaGetSymbolAddress((void**)&Wf1, g_Wf1);
    cudaGetSymbolAddress((void**)&Wf2, g_Wf2);
    cudaGetSymbolAddress((void**)&h,  g_h);

    prep_grid<<<1, 32>>>(grid);                                              // 0
    prep_weights<<<32, 256>>>(base_w1, spline_w1, scaler1, Wh1, Wl1, Wf1);   // 1
    prep_weights<<<32, 256>>>(base_w2, spline_w2, scaler2, Wh2, Wl2, Wf2);   // 2

    size_t smemL = SM_WORDS * 4;   // 149504 B
    cudaFuncSetAttribute(kan_tc, cudaFuncAttributeMaxDynamicSharedMemorySize, (int)smemL);

    float* emb = (float*)d_out;
    kan_tc<<<n / TILE_M, NTHR, smemL>>>(x, Wh1, Wl1, h);                     // 3  <- ncu capture
    kan_tc<<<n / TILE_M, NTHR, smemL>>>(h, Wh2, Wl2, emb);                   // 4

    if (out_size >= n * HIDDEN + n) {
        float* assign = emb + (size_t)n * HIDDEN;
        prep_protos<<<32, 256>>>(protos);                                    // 5
        reset_cnt<<<1, 32>>>();                                              // 6
        size_t smemC = (size_t)(128 * 129 + 64 * 129) * sizeof(float);
        cudaFuncSetAttribute(cluster_kernel, cudaFuncAttributeMaxDynamicSharedMemorySize, (int)smemC);
        cluster_kernel<<<n / 128, 256, smemC>>>(emb, assign);                // 7
        size_t smemF = 45056 * sizeof(float);
        cudaFuncSetAttribute(fixup_kernel, cudaFuncAttributeMaxDynamicSharedMemorySize, (int)smemF);
        fixup_kernel<<<(n + 31) / 32, 256, smemF>>>(x, Wf1, Wf2, assign);    // 8
    }
}

// round 14
// speedup vs baseline: 1.0265x; 1.0265x over previous
#include <cuda_runtime.h>
#include <cuda_fp16.h>
#include <cstdint>

#define HIDDEN 128
#define NCOEF  8
#define NPROTO 256
#define NMAX   131072
#define TILE_M 128
#define NCHUNK 36            // 4 silu chunks + 32 spline chunks (4 i-cols x 8 c each)
#define KDIM   1152
#define TAU    4e-4f
#define NTHR   512
#define XSS    132           // padded xs row stride (conflict-free: 132 % 32 = 4)
#define PSS    132           // cluster padded stride

// ---------------- device scratch ----------------
__device__ uint32_t g_Wh1[NCHUNK * 2048];
__device__ uint32_t g_Wl1[NCHUNK * 2048];
__device__ uint32_t g_Wh2[NCHUNK * 2048];
__device__ uint32_t g_Wl2[NCHUNK * 2048];
__device__ float g_Wf1[KDIM * HIDDEN];     // fp32 combined, [k][o] (fixup)
__device__ float g_Wf2[KDIM * HIDDEN];
__device__ float g_h[(size_t)NMAX * HIDDEN];
__device__ float g_pn[NPROTO * HIDDEN];
__device__ float g_pnT[HIDDEN * NPROTO];
__device__ float g_gp[2];                  // g0, invh
__device__ int   g_cnt;
__device__ int   g_list[NMAX];

// ---------------- helpers ----------------
__device__ __forceinline__ uint32_t smem_u32p(const void* p) {
    uint32_t a;
    asm("{ .reg .u64 t; cvta.to.shared.u64 t, %1; cvt.u32.u64 %0, t; }" : "=r"(a) : "l"(p));
    return a;
}
__device__ __forceinline__ uint32_t h2_split2(float v0, float v1, uint32_t& lo_out) {
    __half2 hp = __float22half2_rn(make_float2(v0, v1));
    float2 hf = __half22float2(hp);
    __half2 lp = __float22half2_rn(make_float2(v0 - hf.x, v1 - hf.y));
    lo_out = *(uint32_t*)&lp;
    return *(uint32_t*)&hp;
}
__device__ __forceinline__ void mma16(float* c, const uint32_t* a, const uint32_t* b) {
    asm volatile(
        "mma.sync.aligned.m16n8k16.row.col.f32.f16.f16.f32 "
        "{%0,%1,%2,%3}, {%4,%5,%6,%7}, {%8,%9}, {%0,%1,%2,%3};"
        : "+f"(c[0]), "+f"(c[1]), "+f"(c[2]), "+f"(c[3])
        : "r"(a[0]), "r"(a[1]), "r"(a[2]), "r"(a[3]), "r"(b[0]), "r"(b[1]));
}
#define LDSM_X4(r, a)                                                         \
    asm volatile("ldmatrix.sync.aligned.m8n8.x4.shared.b16 {%0,%1,%2,%3}, [%4];" \
        : "=r"((r)[0]), "=r"((r)[1]), "=r"((r)[2]), "=r"((r)[3]) : "r"(a))

__device__ __forceinline__ float bspline_c(float xv, int c, float g0, float invh) {
    float t = (xv - g0) * invh;
    float fj = floorf(t);
    float u = t - fj;
    int d = (int)fj - c;
    float v;
    if (d == 0)      v = u * u * u * (1.0f / 6.0f);
    else if (d == 1) v = (1.0f + 3.0f * u + 3.0f * u * u - 3.0f * u * u * u) * (1.0f / 6.0f);
    else if (d == 2) { float w = 1.0f - u; v = (1.0f + 3.0f * w + 3.0f * w * w - 3.0f * w * w * w) * (1.0f / 6.0f); }
    else if (d == 3) { float w = 1.0f - u; v = w * w * w * (1.0f / 6.0f); }
    else             v = 0.0f;
    return v;
}

// ---------------- prep kernels ----------------
__global__ void prep_grid(const float* __restrict__ grid) {
    if (threadIdx.x == 0) {
        g_gp[0] = grid[0];
        g_gp[1] = 1.0f / (grid[1] - grid[0]);
    }
}

// k-layout:
//  silu:   kc = i>>5 (0..3), kp = (i&31)>>1, half-lane = i&1
//  spline: kc = 4 + (i>>2) (4..35), kp = (i&3)*4 + (c>>1), half-lane = c&1
__global__ void prep_weights(const float* __restrict__ base_w,
                             const float* __restrict__ spline_w,
                             const float* __restrict__ scaler,
                             uint32_t* __restrict__ Wh, uint32_t* __restrict__ Wl,
                             float* __restrict__ Wf) {
    int idx = blockIdx.x * blockDim.x + threadIdx.x;
    if (idx >= HIDDEN * 64) return;
    int o = idx >> 6, m = idx & 63;
    int i0 = 2 * m, i1 = 2 * m + 1;
    int iq = m >> 4, kp = m & 15;

    float w0 = base_w[o * HIDDEN + i0];
    float w1 = base_w[o * HIDDEN + i1];
    uint32_t lo, hi = h2_split2(w0, w1, lo);
    Wh[iq * 2048 + o * 16 + kp] = hi;
    Wl[iq * 2048 + o * 16 + kp] = lo;
    Wf[(size_t)i0 * HIDDEN + o] = w0;
    Wf[(size_t)i1 * HIDDEN + o] = w1;

    float sc0 = scaler[o * HIDDEN + i0];
    float sc1 = scaler[o * HIDDEN + i1];
    int kcS = 4 + (i0 >> 2);   // same chunk for i0 and i1 (i0 even)
#pragma unroll
    for (int cp = 0; cp < 4; cp++) {
        float s0 = spline_w[(o * HIDDEN + i0) * NCOEF + 2 * cp]     * sc0;
        float s1 = spline_w[(o * HIDDEN + i0) * NCOEF + 2 * cp + 1] * sc0;
        hi = h2_split2(s0, s1, lo);
        int kp0 = (i0 & 3) * 4 + cp;
        Wh[kcS * 2048 + o * 16 + kp0] = hi;
        Wl[kcS * 2048 + o * 16 + kp0] = lo;
        Wf[(size_t)(HIDDEN + 2 * cp * HIDDEN + i0) * HIDDEN + o]       = s0;
        Wf[(size_t)(HIDDEN + (2 * cp + 1) * HIDDEN + i0) * HIDDEN + o] = s1;
        float s2 = spline_w[(o * HIDDEN + i1) * NCOEF + 2 * cp]     * sc1;
        float s3 = spline_w[(o * HIDDEN + i1) * NCOEF + 2 * cp + 1] * sc1;
        hi = h2_split2(s2, s3, lo);
        int kp1 = (i1 & 3) * 4 + cp;
        Wh[kcS * 2048 + o * 16 + kp1] = hi;
        Wl[kcS * 2048 + o * 16 + kp1] = lo;
        Wf[(size_t)(HIDDEN + 2 * cp * HIDDEN + i1) * HIDDEN + o]       = s2;
        Wf[(size_t)(HIDDEN + (2 * cp + 1) * HIDDEN + i1) * HIDDEN + o] = s3;
    }
}

__global__ void prep_protos(const float* __restrict__ protos) {
    int w = (blockIdx.x * blockDim.x + threadIdx.x) >> 5;
    int lane = threadIdx.x & 31;
    if (w >= NPROTO) return;
    float ss = 0.f;
    for (int i = lane; i < HIDDEN; i += 32) {
        float v = protos[w * HIDDEN + i];
        ss += v * v;
    }
#pragma unroll
    for (int off = 16; off; off >>= 1) ss += __shfl_xor_sync(0xffffffffu, ss, off);
    float inv = 1.0f / fmaxf(sqrtf(ss), 1e-8f);
    for (int i = lane; i < HIDDEN; i += 32) {
        float v = protos[w * HIDDEN + i] * inv;
        g_pn[w * HIDDEN + i] = v;
        g_pnT[i * NPROTO + w] = v;
    }
}

__global__ void reset_cnt() { g_cnt = 0; }

// ---------------- fused KAN layer ----------------
#define U_SA  (TILE_M * XSS)             // 16896
#define U_SB  (U_SA + 10240)
#define SM_WORDS (U_SB + 10240)          // 37376 u32 = 149504 B

__global__ void __launch_bounds__(NTHR, 1)
kan_tc(const float* __restrict__ in,
       const uint32_t* __restrict__ Wh, const uint32_t* __restrict__ Wl,
       float* __restrict__ out) {
    extern __shared__ float sm[];
    float* xs = sm;
    uint32_t* u32b = (uint32_t*)sm;

    const int tid  = threadIdx.x;
    const int lane = tid & 31;
    const int wid  = tid >> 5;        // 0..15
    const int wr   = wid >> 2;        // 0..3  rows wr*32
    const int wc   = wid & 3;         // 0..3  cols wc*32

    const float g0 = g_gp[0], invh = g_gp[1];
    const int m0 = blockIdx.x * TILE_M;

    // ldmatrix per-lane address bases (byte offsets into dynamic smem)
    const uint32_t smb = smem_u32p(sm);
    const int arow  = wr * 32 + ((lane >> 3) & 1) * 8 + (lane & 7);
    const int akoff = ((lane >> 4) & 1) * 4;
    const uint32_t aAddr0 = smb + 4u * (U_SA + arow * 20 + akoff);
    const int bcol  = wc * 32 + ((lane >> 4) & 1) * 8 + (lane & 7);
    const int bkoff = ((lane >> 3) & 1) * 4;
    const uint32_t bAddr0 = smb + 4u * (U_SB + bcol * 20 + bkoff);

    {   // x tile load into padded rows (stride XSS)
        const float4* src = (const float4*)(in + (size_t)m0 * HIDDEN);
#pragma unroll
        for (int j = 0; j < 8; j++) {
            int f = tid + j * NTHR;          // float4 id: r*32 + c4
            int r = f >> 5, c4 = f & 31;
            *(float4*)(xs + r * XSS + c4 * 4) = src[f];
        }
    }
    __syncthreads();

    float acc[2][4][4];
#pragma unroll
    for (int a = 0; a < 2; a++)
#pragma unroll
        for (int b = 0; b < 4; b++)
#pragma unroll
            for (int c = 0; c < 4; c++) acc[a][b][c] = 0.f;

#define STAGE(kc_, bb_) do {                                                         \
        uint32_t* dBh = u32b + U_SB + (bb_) * 5120;                                  \
        uint32_t* dBl = dBh + 2560;                                                  \
        const uint2* sh = (const uint2*)(Wh + (kc_) * 2048);                         \
        const uint2* sl = (const uint2*)(Wl + (kc_) * 2048);                         \
        _Pragma("unroll")                                                            \
        for (int j = 0; j < 2; j++) {                                                \
            int f2 = tid + j * NTHR;                                                 \
            int n = f2 >> 3, kp2 = f2 & 7;                                           \
            ((uint2*)(dBh + n * 20))[kp2] = sh[f2];                                  \
            ((uint2*)(dBl + n * 20))[kp2] = sl[f2];                                  \
        }                                                                            \
        uint32_t* dAh = u32b + U_SA + (bb_) * 5120;                                  \
        uint32_t* dAl = dAh + 2560;                                                  \
        if ((kc_) < 4) {                                                             \
            int ibase = (kc_) * 32;                                                  \
            _Pragma("unroll")                                                        \
            for (int j = 0; j < 4; j++) {                                            \
                int p = tid + j * NTHR;                                              \
                int r = p >> 4, kp = p & 15;                                         \
                float2 xv = *(const float2*)(xs + r * XSS + ibase + 2 * kp);         \
                float v0 = xv.x / (1.0f + __expf(-xv.x));                            \
                float v1 = xv.y / (1.0f + __expf(-xv.y));                            \
                uint32_t lo2, hi2 = h2_split2(v0, v1, lo2);                          \
                dAh[r * 20 + kp] = hi2;                                              \
                dAl[r * 20 + kp] = lo2;                                              \
            }                                                                        \
        } else {                                                                     \
            int ibase = ((kc_) - 4) * 4;                                             \
            int r = tid >> 2, q = tid & 3;                                           \
            float xv = xs[r * XSS + ibase + q];                                      \
            float t  = (xv - g0) * invh;                                             \
            float fj = floorf(t);                                                    \
            float u  = t - fj;                                                       \
            int jc   = (int)fj;                                                      \
            float u2 = u * u, u3 = u2 * u;                                           \
            float wd0 = u3 * (1.0f / 6.0f);                                          \
            float wd1 = (1.0f + 3.0f * u + 3.0f * u2 - 3.0f * u3) * (1.0f / 6.0f);   \
            float wm = 1.0f - u;                                                     \
            float wm2 = wm * wm;                                                     \
            float wd2 = (1.0f + 3.0f * wm + 3.0f * wm2 - 3.0f * wm2 * wm) * (1.0f / 6.0f); \
            float wd3 = wm2 * wm * (1.0f / 6.0f);                                    \
            float val[8];                                                            \
            _Pragma("unroll")                                                        \
            for (int c = 0; c < 8; c++) {                                            \
                float v = 0.f;                                                       \
                v = (jc == c)     ? wd0 : v;                                         \
                v = (jc == c + 1) ? wd1 : v;                                         \
                v = (jc == c + 2) ? wd2 : v;                                         \
                v = (jc == c + 3) ? wd3 : v;                                         \
                val[c] = v;                                                          \
            }                                                                        \
            uint32_t h0, h1, h2, h3, l0, l1, l2, l3;                                 \
            h0 = h2_split2(val[0], val[1], l0);                                      \
            h1 = h2_split2(val[2], val[3], l1);                                      \
            h2 = h2_split2(val[4], val[5], l2);                                      \
            h3 = h2_split2(val[6], val[7], l3);                                      \
            *(uint4*)(dAh + r * 20 + q * 4) = make_uint4(h0, h1, h2, h3);            \
            *(uint4*)(dAl + r * 20 + q * 4) = make_uint4(l0, l1, l2, l3);            \
        }                                                                            \
    } while (0)

    STAGE(0, 0);
    __syncthreads();

    for (int kc = 0; kc < NCHUNK; kc++) {
        const int b = kc & 1;
        if (kc < NCHUNK - 1) STAGE(kc + 1, b ^ 1);

        const uint32_t aB = aAddr0 + (uint32_t)b * 20480u;   // b*5120 u32
        const uint32_t bB = bAddr0 + (uint32_t)b * 20480u;

#pragma unroll
        for (int ks = 0; ks < 2; ks++) {
            const uint32_t kso = (uint32_t)ks * 32u;         // ks*8 u32
            uint32_t bh[8], bl[8];
            LDSM_X4(bh + 0, bB + kso);                        // nf0, nf1 (hi)
            LDSM_X4(bh + 4, bB + 1280u + kso);                // nf2, nf3 (hi)
            LDSM_X4(bl + 0, bB + 10240u + kso);               // nf0, nf1 (lo)
            LDSM_X4(bl + 4, bB + 10240u + 1280u + kso);       // nf2, nf3 (lo)
#pragma unroll
            for (int mf = 0; mf < 2; mf++) {
                uint32_t ah[4], al[4];
                LDSM_X4(ah, aB + (uint32_t)mf * 1280u + kso);
                LDSM_X4(al, aB + 10240u + (uint32_t)mf * 1280u + kso);
#pragma unroll
                for (int nf = 0; nf < 4; nf++) {
                    mma16(acc[mf][nf], ah, bh + nf * 2);
                    mma16(acc[mf][nf], ah, bl + nf * 2);
                    mma16(acc[mf][nf], al, bh + nf * 2);
                }
            }
        }
        __syncthreads();
    }

#pragma unroll
    for (int mf = 0; mf < 2; mf++) {
        int row = m0 + wr * 32 + mf * 16 + (lane >> 2);
#pragma unroll
        for (int nf = 0; nf < 4; nf++) {
            int col = wc * 32 + nf * 8 + (lane & 3) * 2;
            *(float2*)(out + (size_t)row * HIDDEN + col) =
                make_float2(acc[mf][nf][0], acc[mf][nf][1]);
            *(float2*)(out + (size_t)(row + 8) * HIDDEN + col) =
                make_float2(acc[mf][nf][2], acc[mf][nf][3]);
        }
    }
}

// ---------------- cluster v3: float4 LDS, padded stride, 2 blocks/SM ----------------
// block: 128 rows x 256 protos (4 tiles of 64); 256 thr; thread = 4 rows x 8 protos
// smem: sR[128][132] | sP[64][132] = 101376 B  -> 2 blocks/SM
__global__ void __launch_bounds__(256, 2)
cluster_kernel(const float* __restrict__ emb, float* __restrict__ assignOut) {
    extern __shared__ float sm[];
    float* sR = sm;                  // 128*PSS
    float* sP = sm + 128 * PSS;      // 64*PSS

    const int tid = threadIdx.x;
    const int rg  = tid >> 3;        // 0..31
    const int pg  = tid & 7;         // 0..7
    const int base = blockIdx.x * 128;

    {
        const float4* esrc = (const float4*)(emb + (size_t)base * HIDDEN);
#pragma unroll
        for (int j = 0; j < 16; j++) {
            int f = tid + j * 256;
            int r = f >> 5, c4 = f & 31;
            *(float4*)(sR + r * PSS + c4 * 4) = esrc[f];
        }
    }

    float t1[4], t2[4];
    int   i1[4];
#pragma unroll
    for (int j = 0; j < 4; j++) { t1[j] = -3.4e38f; t2[j] = -3.4e38f; i1[j] = 0; }

    for (int pq = 0; pq < 4; pq++) {
        __syncthreads();
        {
            const float4* psrc = (const float4*)(g_pn + (size_t)(pq * 64) * HIDDEN);
#pragma unroll
            for (int j = 0; j < 8; j++) {
                int f = tid + j * 256;
                int p = f >> 5, c4 = f & 31;
                *(float4*)(sP + p * PSS + c4 * 4) = psrc[f];
            }
        }
        __syncthreads();

        float acc[4][8];
#pragma unroll
        for (int j = 0; j < 4; j++)
#pragma unroll
            for (int jj = 0; jj < 8; jj++) acc[j][jj] = 0.f;

        const float* rbase = sR + (rg * 4) * PSS;
        const float* pbase = sP + pg * PSS;
        for (int k = 0; k < HIDDEN; k += 4) {
            float4 rv[4], pv[8];
#pragma unroll
            for (int j = 0; j < 4; j++)
                rv[j] = *(const float4*)(rbase + j * PSS + k);
#pragma unroll
            for (int jj = 0; jj < 8; jj++)
                pv[jj] = *(const float4*)(pbase + jj * 8 * PSS + k);
#pragma unroll
            for (int j = 0; j < 4; j++)
#pragma unroll
                for (int jj = 0; jj < 8; jj++) {
                    acc[j][jj] += rv[j].x * pv[jj].x;
                    acc[j][jj] += rv[j].y * pv[jj].y;
                    acc[j][jj] += rv[j].z * pv[jj].z;
                    acc[j][jj] += rv[j].w * pv[jj].w;
                }
        }

#pragma unroll
        for (int j = 0; j < 4; j++) {
#pragma unroll
            for (int jj = 0; jj < 8; jj++) {
                float v = acc[j][jj];
                int idx = pq * 64 + jj * 8 + pg;
                if (v > t1[j]) { t2[j] = t1[j]; t1[j] = v; i1[j] = idx; }
                else if (v > t2[j]) { t2[j] = v; }
            }
        }
    }

#pragma unroll
    for (int j = 0; j < 4; j++) {
        float a1 = t1[j], a2 = t2[j];
        int   ai = i1[j];
#pragma unroll
        for (int off = 4; off; off >>= 1) {
            float b1 = __shfl_down_sync(0xffffffffu, a1, off, 8);
            float b2 = __shfl_down_sync(0xffffffffu, a2, off, 8);
            int   bi = __shfl_down_sync(0xffffffffu, ai, off, 8);
            if (b1 > a1 || (b1 == a1 && bi < ai)) {
                a2 = fmaxf(a1, b2); a1 = b1; ai = bi;
            } else {
                a2 = fmaxf(a2, b1);
            }
        }
        t1[j] = a1; t2[j] = a2; i1[j] = ai;
    }

    if (pg == 0) {
#pragma unroll
        for (int j = 0; j < 4; j++) {
            int row = base + rg * 4 + j;
            assignOut[row] = (float)i1[j];
            if (t1[j] - t2[j] < TAU) {
                int s = atomicAdd(&g_cnt, 1);
                g_list[s] = row;
            }
        }
    }
}

// ---------------- fp32 fixup ----------------
__global__ void __launch_bounds__(256, 1)
fixup_kernel(const float* __restrict__ x,
             const float* __restrict__ Wf1, const float* __restrict__ Wf2,
             float* __restrict__ assignOut) {
    extern __shared__ float sm[];
    float* A  = sm;                 // 36864
    float* hb = sm + 36864;         // 4096
    float* ws = sm + 40960;         // 4096
    __shared__ int ridx[32];
    __shared__ float rv[8];
    __shared__ int   rp[8];

    const int tid = threadIdx.x;
    const int start = blockIdx.x * 32;
    const int cnt = g_cnt;
    if (start >= cnt) return;
    const int nr = min(32, cnt - start);
    if (tid < 32) {
        int srci = start + (tid < nr ? tid : nr - 1);
        ridx[tid] = g_list[srci];
    }
    __syncthreads();

    const float g0 = g_gp[0], invh = g_gp[1];
    const int tr = tid >> 5;
    const int tc = tid & 31;

    float acc[4][4];
    const float* Wf = Wf1;
    const float* src = x;
    bool gather = true;

    for (int layer = 0; layer < 2; layer++) {
        for (int e = tid; e < 32 * HIDDEN; e += 256) {
            int r = e >> 7, i = e & 127;
            float xv = gather ? src[(size_t)ridx[r] * HIDDEN + i] : src[r * HIDDEN + i];
            A[r * KDIM + i] = xv / (1.0f + __expf(-xv));
#pragma unroll
            for (int c = 0; c < NCOEF; c++)
                A[r * KDIM + HIDDEN + c * HIDDEN + i] = bspline_c(xv, c, g0, invh);
        }

#pragma unroll
        for (int a = 0; a < 4; a++)
#pragma unroll
            for (int b = 0; b < 4; b++) acc[a][b] = 0.f;

        for (int k0 = 0; k0 < KDIM; k0 += 32) {
            __syncthreads();
            const float4* gw = (const float4*)(Wf + (size_t)k0 * HIDDEN);
#pragma unroll
            for (int l = 0; l < 4; l++)
                ((float4*)ws)[tid + l * 256] = gw[tid + l * 256];
            __syncthreads();
#pragma unroll
            for (int kk = 0; kk < 32; kk++) {
                float a0 = A[(tr * 4 + 0) * KDIM + k0 + kk];
                float a1 = A[(tr * 4 + 1) * KDIM + k0 + kk];
                float a2 = A[(tr * 4 + 2) * KDIM + k0 + kk];
                float a3 = A[(tr * 4 + 3) * KDIM + k0 + kk];
                float4 w = ((float4*)ws)[kk * 32 + tc];
                acc[0][0] += a0 * w.x; acc[0][1] += a0 * w.y; acc[0][2] += a0 * w.z; acc[0][3] += a0 * w.w;
                acc[1][0] += a1 * w.x; acc[1][1] += a1 * w.y; acc[1][2] += a1 * w.z; acc[1][3] += a1 * w.w;
                acc[2][0] += a2 * w.x; acc[2][1] += a2 * w.y; acc[2][2] += a2 * w.z; acc[2][3] += a2 * w.w;
                acc[3][0] += a3 * w.x; acc[3][1] += a3 * w.y; acc[3][2] += a3 * w.z; acc[3][3] += a3 * w.w;
            }
        }
        __syncthreads();
#pragma unroll
        for (int ri = 0; ri < 4; ri++)
            ((float4*)(hb + (tr * 4 + ri) * HIDDEN))[tc] =
                make_float4(acc[ri][0], acc[ri][1], acc[ri][2], acc[ri][3]);
        __syncthreads();

        Wf = Wf2; src = hb; gather = false;
    }

    float sims[32];
#pragma unroll
    for (int r = 0; r < 32; r++) sims[r] = 0.f;
    for (int i = 0; i < HIDDEN; i++) {
        float pv = g_pnT[i * NPROTO + tid];
#pragma unroll
        for (int r = 0; r < 32; r++) sims[r] += hb[r * HIDDEN + i] * pv;
    }

    for (int r = 0; r < 32; r++) {
        float v = sims[r]; int bi = tid;
#pragma unroll
        for (int off = 16; off; off >>= 1) {
            float ov = __shfl_down_sync(0xffffffffu, v, off);
            int   oi = __shfl_down_sync(0xffffffffu, bi, off);
            if (ov > v || (ov == v && oi < bi)) { v = ov; bi = oi; }
        }
        if ((tid & 31) == 0) { rv[tid >> 5] = v; rp[tid >> 5] = bi; }
        __syncthreads();
        if (tid == 0) {
            float bv = rv[0]; int bb = rp[0];
#pragma unroll
            for (int w = 1; w < 8; w++)
                if (rv[w] > bv || (rv[w] == bv && rp[w] < bb)) { bv = rv[w]; bb = rp[w]; }
            if (r < nr) assignOut[ridx[r]] = (float)bb;
        }
        __syncthreads();
    }
}

// ---------------- launch ----------------
extern "C" void kernel_launch(void* const* d_in, const int* in_sizes, int n_in,
                              void* d_out, int out_size) {
    const float* x         = (const float*)d_in[0];
    const float* protos    = (const float*)d_in[1];
    const float* grid      = (const float*)d_in[2];
    const float* base_w1   = (const float*)d_in[3];
    const float* spline_w1 = (const float*)d_in[4];
    const float* scaler1   = (const float*)d_in[5];
    const float* base_w2   = (const float*)d_in[6];
    const float* spline_w2 = (const float*)d_in[7];
    const float* scaler2   = (const float*)d_in[8];

    int n = in_sizes[0] / HIDDEN;

    uint32_t *Wh1, *Wl1, *Wh2, *Wl2;
    float *Wf1, *Wf2, *h;
    cudaGetSymbolAddress((void**)&Wh1, g_Wh1);
    cudaGetSymbolAddress((void**)&Wl1, g_Wl1);
    cudaGetSymbolAddress((void**)&Wh2, g_Wh2);
    cudaGetSymbolAddress((void**)&Wl2, g_Wl2);
    cudaGetSymbolAddress((void**)&Wf1, g_Wf1);
    cudaGetSymbolAddress((void**)&Wf2, g_Wf2);
    cudaGetSymbolAddress((void**)&h,  g_h);

    prep_grid<<<1, 32>>>(grid);                                              // 0
    prep_weights<<<32, 256>>>(base_w1, spline_w1, scaler1, Wh1, Wl1, Wf1);   // 1
    prep_weights<<<32, 256>>>(base_w2, spline_w2, scaler2, Wh2, Wl2, Wf2);   // 2

    size_t smemL = SM_WORDS * 4;   // 149504 B
    cudaFuncSetAttribute(kan_tc, cudaFuncAttributeMaxDynamicSharedMemorySize, (int)smemL);

    float* emb = (float*)d_out;
    kan_tc<<<n / TILE_M, NTHR, smemL>>>(x, Wh1, Wl1, h);                     // 3  <- ncu capture
    kan_tc<<<n / TILE_M, NTHR, smemL>>>(h, Wh2, Wl2, emb);                   // 4

    if (out_size >= n * HIDDEN + n) {
        float* assign = emb + (size_t)n * HIDDEN;
        prep_protos<<<32, 256>>>(protos);                                    // 5
        reset_cnt<<<1, 32>>>();                                              // 6
        size_t smemC = (size_t)(192 * PSS) * sizeof(float);                  // 101376 B
        cudaFuncSetAttribute(cluster_kernel, cudaFuncAttributeMaxDynamicSharedMemorySize, (int)smemC);
        cluster_kernel<<<n / 128, 256, smemC>>>(emb, assign);                // 7
        size_t smemF = 45056 * sizeof(float);
        cudaFuncSetAttribute(fixup_kernel, cudaFuncAttributeMaxDynamicSharedMemorySize, (int)smemF);
        fixup_kernel<<<(n + 31) / 32, 256, smemF>>>(x, Wf1, Wf2, assign);    // 8
    }
}

// round 15
// speedup vs baseline: 1.1589x; 1.1289x over previous
#include <cuda_runtime.h>
#include <cuda_fp16.h>
#include <cstdint>

#define HIDDEN 128
#define NCOEF  8
#define NPROTO 256
#define NMAX   131072
#define TILE_M 128
#define NCHUNK 36            // 4 silu chunks + 32 spline chunks (4 i-cols x 8 c each)
#define KDIM   1152
#define TAU    4e-4f
#define NTHR   512
#define XSS    132           // padded xs row stride (conflict-free: 132 % 32 = 4)
#define CSS    68            // cluster smem row stride (u32): 68 % 32 = 4, 272 B = 16B-aligned

// ---------------- device scratch ----------------
__device__ uint32_t g_Wh1[NCHUNK * 2048];
__device__ uint32_t g_Wl1[NCHUNK * 2048];
__device__ uint32_t g_Wh2[NCHUNK * 2048];
__device__ uint32_t g_Wl2[NCHUNK * 2048];
__device__ float g_Wf1[KDIM * HIDDEN];     // fp32 combined, [k][o] (fixup)
__device__ float g_Wf2[KDIM * HIDDEN];
__device__ float g_h[(size_t)NMAX * HIDDEN];
__device__ float g_pnT[HIDDEN * NPROTO];   // normalized protos transposed (fixup)
__device__ uint32_t g_pnh[NPROTO * 64];    // normalized protos, packed half2 k-pairs, hi
__device__ uint32_t g_pnl[NPROTO * 64];    // lo
__device__ float g_gp[2];                  // g0, invh
__device__ int   g_cnt;
__device__ int   g_list[NMAX];

// ---------------- helpers ----------------
__device__ __forceinline__ uint32_t smem_u32p(const void* p) {
    uint32_t a;
    asm("{ .reg .u64 t; cvta.to.shared.u64 t, %1; cvt.u32.u64 %0, t; }" : "=r"(a) : "l"(p));
    return a;
}
__device__ __forceinline__ uint32_t h2_split2(float v0, float v1, uint32_t& lo_out) {
    __half2 hp = __float22half2_rn(make_float2(v0, v1));
    float2 hf = __half22float2(hp);
    __half2 lp = __float22half2_rn(make_float2(v0 - hf.x, v1 - hf.y));
    lo_out = *(uint32_t*)&lp;
    return *(uint32_t*)&hp;
}
__device__ __forceinline__ void mma16(float* c, const uint32_t* a, const uint32_t* b) {
    asm volatile(
        "mma.sync.aligned.m16n8k16.row.col.f32.f16.f16.f32 "
        "{%0,%1,%2,%3}, {%4,%5,%6,%7}, {%8,%9}, {%0,%1,%2,%3};"
        : "+f"(c[0]), "+f"(c[1]), "+f"(c[2]), "+f"(c[3])
        : "r"(a[0]), "r"(a[1]), "r"(a[2]), "r"(a[3]), "r"(b[0]), "r"(b[1]));
}
#define LDSM_X4(r, a)                                                         \
    asm volatile("ldmatrix.sync.aligned.m8n8.x4.shared.b16 {%0,%1,%2,%3}, [%4];" \
        : "=r"((r)[0]), "=r"((r)[1]), "=r"((r)[2]), "=r"((r)[3]) : "r"(a))

__device__ __forceinline__ float bspline_c(float xv, int c, float g0, float invh) {
    float t = (xv - g0) * invh;
    float fj = floorf(t);
    float u = t - fj;
    int d = (int)fj - c;
    float v;
    if (d == 0)      v = u * u * u * (1.0f / 6.0f);
    else if (d == 1) v = (1.0f + 3.0f * u + 3.0f * u * u - 3.0f * u * u * u) * (1.0f / 6.0f);
    else if (d == 2) { float w = 1.0f - u; v = (1.0f + 3.0f * w + 3.0f * w * w - 3.0f * w * w * w) * (1.0f / 6.0f); }
    else if (d == 3) { float w = 1.0f - u; v = w * w * w * (1.0f / 6.0f); }
    else             v = 0.0f;
    return v;
}

// ---------------- prep kernels ----------------
__global__ void prep_grid(const float* __restrict__ grid) {
    if (threadIdx.x == 0) {
        g_gp[0] = grid[0];
        g_gp[1] = 1.0f / (grid[1] - grid[0]);
    }
}

// k-layout (kan layers):
//  silu:   kc = i>>5 (0..3), kp = (i&31)>>1, half-lane = i&1
//  spline: kc = 4 + (i>>2) (4..35), kp = (i&3)*4 + (c>>1), half-lane = c&1
__global__ void prep_weights(const float* __restrict__ base_w,
                             const float* __restrict__ spline_w,
                             const float* __restrict__ scaler,
                             uint32_t* __restrict__ Wh, uint32_t* __restrict__ Wl,
                             float* __restrict__ Wf) {
    int idx = blockIdx.x * blockDim.x + threadIdx.x;
    if (idx >= HIDDEN * 64) return;
    int o = idx >> 6, m = idx & 63;
    int i0 = 2 * m, i1 = 2 * m + 1;
    int iq = m >> 4, kp = m & 15;

    float w0 = base_w[o * HIDDEN + i0];
    float w1 = base_w[o * HIDDEN + i1];
    uint32_t lo, hi = h2_split2(w0, w1, lo);
    Wh[iq * 2048 + o * 16 + kp] = hi;
    Wl[iq * 2048 + o * 16 + kp] = lo;
    Wf[(size_t)i0 * HIDDEN + o] = w0;
    Wf[(size_t)i1 * HIDDEN + o] = w1;

    float sc0 = scaler[o * HIDDEN + i0];
    float sc1 = scaler[o * HIDDEN + i1];
    int kcS = 4 + (i0 >> 2);   // same chunk for i0 and i1 (i0 even)
#pragma unroll
    for (int cp = 0; cp < 4; cp++) {
        float s0 = spline_w[(o * HIDDEN + i0) * NCOEF + 2 * cp]     * sc0;
        float s1 = spline_w[(o * HIDDEN + i0) * NCOEF + 2 * cp + 1] * sc0;
        hi = h2_split2(s0, s1, lo);
        int kp0 = (i0 & 3) * 4 + cp;
        Wh[kcS * 2048 + o * 16 + kp0] = hi;
        Wl[kcS * 2048 + o * 16 + kp0] = lo;
        Wf[(size_t)(HIDDEN + 2 * cp * HIDDEN + i0) * HIDDEN + o]       = s0;
        Wf[(size_t)(HIDDEN + (2 * cp + 1) * HIDDEN + i0) * HIDDEN + o] = s1;
        float s2 = spline_w[(o * HIDDEN + i1) * NCOEF + 2 * cp]     * sc1;
        float s3 = spline_w[(o * HIDDEN + i1) * NCOEF + 2 * cp + 1] * sc1;
        hi = h2_split2(s2, s3, lo);
        int kp1 = (i1 & 3) * 4 + cp;
        Wh[kcS * 2048 + o * 16 + kp1] = hi;
        Wl[kcS * 2048 + o * 16 + kp1] = lo;
        Wf[(size_t)(HIDDEN + 2 * cp * HIDDEN + i1) * HIDDEN + o]       = s2;
        Wf[(size_t)(HIDDEN + (2 * cp + 1) * HIDDEN + i1) * HIDDEN + o] = s3;
    }
}

__global__ void prep_protos(const float* __restrict__ protos) {
    int w = (blockIdx.x * blockDim.x + threadIdx.x) >> 5;
    int lane = threadIdx.x & 31;
    if (w >= NPROTO) return;
    float ss = 0.f;
    for (int i = lane; i < HIDDEN; i += 32) {
        float v = protos[w * HIDDEN + i];
        ss += v * v;
    }
#pragma unroll
    for (int off = 16; off; off >>= 1) ss += __shfl_xor_sync(0xffffffffu, ss, off);
    float inv = 1.0f / fmaxf(sqrtf(ss), 1e-8f);
    for (int i = lane; i < HIDDEN; i += 32)
        g_pnT[i * NPROTO + w] = protos[w * HIDDEN + i] * inv;
    for (int m = lane; m < 64; m += 32) {
        float v0 = protos[w * HIDDEN + 2 * m] * inv;
        float v1 = protos[w * HIDDEN + 2 * m + 1] * inv;
        uint32_t lo, hi = h2_split2(v0, v1, lo);
        g_pnh[w * 64 + m] = hi;
        g_pnl[w * 64 + m] = lo;
    }
}

__global__ void reset_cnt() { g_cnt = 0; }

// ---------------- fused KAN layer ----------------
#define U_SA  (TILE_M * XSS)             // 16896
#define U_SB  (U_SA + 10240)
#define SM_WORDS (U_SB + 10240)          // 37376 u32 = 149504 B

__global__ void __launch_bounds__(NTHR, 1)
kan_tc(const float* __restrict__ in,
       const uint32_t* __restrict__ Wh, const uint32_t* __restrict__ Wl,
       float* __restrict__ out) {
    extern __shared__ float sm[];
    float* xs = sm;
    uint32_t* u32b = (uint32_t*)sm;

    const int tid  = threadIdx.x;
    const int lane = tid & 31;
    const int wid  = tid >> 5;        // 0..15
    const int wr   = wid >> 2;        // 0..3  rows wr*32
    const int wc   = wid & 3;         // 0..3  cols wc*32

    const float g0 = g_gp[0], invh = g_gp[1];
    const int m0 = blockIdx.x * TILE_M;

    const uint32_t smb = smem_u32p(sm);
    const int arow  = wr * 32 + ((lane >> 3) & 1) * 8 + (lane & 7);
    const int akoff = ((lane >> 4) & 1) * 4;
    const uint32_t aAddr0 = smb + 4u * (U_SA + arow * 20 + akoff);
    const int bcol  = wc * 32 + ((lane >> 4) & 1) * 8 + (lane & 7);
    const int bkoff = ((lane >> 3) & 1) * 4;
    const uint32_t bAddr0 = smb + 4u * (U_SB + bcol * 20 + bkoff);

    {   // x tile load into padded rows (stride XSS)
        const float4* src = (const float4*)(in + (size_t)m0 * HIDDEN);
#pragma unroll
        for (int j = 0; j < 8; j++) {
            int f = tid + j * NTHR;          // float4 id: r*32 + c4
            int r = f >> 5, c4 = f & 31;
            *(float4*)(xs + r * XSS + c4 * 4) = src[f];
        }
    }
    __syncthreads();

    float acc[2][4][4];
#pragma unroll
    for (int a = 0; a < 2; a++)
#pragma unroll
        for (int b = 0; b < 4; b++)
#pragma unroll
            for (int c = 0; c < 4; c++) acc[a][b][c] = 0.f;

#define STAGE(kc_, bb_) do {                                                         \
        uint32_t* dBh = u32b + U_SB + (bb_) * 5120;                                  \
        uint32_t* dBl = dBh + 2560;                                                  \
        const uint2* sh = (const uint2*)(Wh + (kc_) * 2048);                         \
        const uint2* sl = (const uint2*)(Wl + (kc_) * 2048);                         \
        _Pragma("unroll")                                                            \
        for (int j = 0; j < 2; j++) {                                                \
            int f2 = tid + j * NTHR;                                                 \
            int n = f2 >> 3, kp2 = f2 & 7;                                           \
            ((uint2*)(dBh + n * 20))[kp2] = sh[f2];                                  \
            ((uint2*)(dBl + n * 20))[kp2] = sl[f2];                                  \
        }                                                                            \
        uint32_t* dAh = u32b + U_SA + (bb_) * 5120;                                  \
        uint32_t* dAl = dAh + 2560;                                                  \
        if ((kc_) < 4) {                                                             \
            int ibase = (kc_) * 32;                                                  \
            _Pragma("unroll")                                                        \
            for (int j = 0; j < 4; j++) {                                            \
                int p = tid + j * NTHR;                                              \
                int r = p >> 4, kp = p & 15;                                         \
                float2 xv = *(const float2*)(xs + r * XSS + ibase + 2 * kp);         \
                float v0 = xv.x / (1.0f + __expf(-xv.x));                            \
                float v1 = xv.y / (1.0f + __expf(-xv.y));                            \
                uint32_t lo2, hi2 = h2_split2(v0, v1, lo2);                          \
                dAh[r * 20 + kp] = hi2;                                              \
                dAl[r * 20 + kp] = lo2;                                              \
            }                                                                        \
        } else {                                                                     \
            int ibase = ((kc_) - 4) * 4;                                             \
            int r = tid >> 2, q = tid & 3;                                           \
            float xv = xs[r * XSS + ibase + q];                                      \
            float t  = (xv - g0) * invh;                                             \
            float fj = floorf(t);                                                    \
            float u  = t - fj;                                                       \
            int jc   = (int)fj;                                                      \
            float u2 = u * u, u3 = u2 * u;                                           \
            float wd0 = u3 * (1.0f / 6.0f);                                          \
            float wd1 = (1.0f + 3.0f * u + 3.0f * u2 - 3.0f * u3) * (1.0f / 6.0f);   \
            float wm = 1.0f - u;                                                     \
            float wm2 = wm * wm;                                                     \
            float wd2 = (1.0f + 3.0f * wm + 3.0f * wm2 - 3.0f * wm2 * wm) * (1.0f / 6.0f); \
            float wd3 = wm2 * wm * (1.0f / 6.0f);                                    \
            float val[8];                                                            \
            _Pragma("unroll")                                                        \
            for (int c = 0; c < 8; c++) {                                            \
                float v = 0.f;                                                       \
                v = (jc == c)     ? wd0 : v;                                         \
                v = (jc == c + 1) ? wd1 : v;                                         \
                v = (jc == c + 2) ? wd2 : v;                                         \
                v = (jc == c + 3) ? wd3 : v;                                         \
                val[c] = v;                                                          \
            }                                                                        \
            uint32_t h0, h1, h2, h3, l0, l1, l2, l3;                                 \
            h0 = h2_split2(val[0], val[1], l0);                                      \
            h1 = h2_split2(val[2], val[3], l1);                                      \
            h2 = h2_split2(val[4], val[5], l2);                                      \
            h3 = h2_split2(val[6], val[7], l3);                                      \
            *(uint4*)(dAh + r * 20 + q * 4) = make_uint4(h0, h1, h2, h3);            \
            *(uint4*)(dAl + r * 20 + q * 4) = make_uint4(l0, l1, l2, l3);            \
        }                                                                            \
    } while (0)

    STAGE(0, 0);
    __syncthreads();

    for (int kc = 0; kc < NCHUNK; kc++) {
        const int b = kc & 1;
        if (kc < NCHUNK - 1) STAGE(kc + 1, b ^ 1);

        const uint32_t aB = aAddr0 + (uint32_t)b * 20480u;   // b*5120 u32
        const uint32_t bB = bAddr0 + (uint32_t)b * 20480u;

#pragma unroll
        for (int ks = 0; ks < 2; ks++) {
            const uint32_t kso = (uint32_t)ks * 32u;         // ks*8 u32
            uint32_t bh[8], bl[8];
            LDSM_X4(bh + 0, bB + kso);
            LDSM_X4(bh + 4, bB + 1280u + kso);
            LDSM_X4(bl + 0, bB + 10240u + kso);
            LDSM_X4(bl + 4, bB + 10240u + 1280u + kso);
#pragma unroll
            for (int mf = 0; mf < 2; mf++) {
                uint32_t ah[4], al[4];
                LDSM_X4(ah, aB + (uint32_t)mf * 1280u + kso);
                LDSM_X4(al, aB + 10240u + (uint32_t)mf * 1280u + kso);
#pragma unroll
                for (int nf = 0; nf < 4; nf++) {
                    mma16(acc[mf][nf], ah, bh + nf * 2);
                    mma16(acc[mf][nf], ah, bl + nf * 2);
                    mma16(acc[mf][nf], al, bh + nf * 2);
                }
            }
        }
        __syncthreads();
    }

#pragma unroll
    for (int mf = 0; mf < 2; mf++) {
        int row = m0 + wr * 32 + mf * 16 + (lane >> 2);
#pragma unroll
        for (int nf = 0; nf < 4; nf++) {
            int col = wc * 32 + nf * 8 + (lane & 3) * 2;
            *(float2*)(out + (size_t)row * HIDDEN + col) =
                make_float2(acc[mf][nf][0], acc[mf][nf][1]);
            *(float2*)(out + (size_t)(row + 8) * HIDDEN + col) =
                make_float2(acc[mf][nf][2], acc[mf][nf][3]);
        }
    }
}

// ---------------- cluster v4: fp16 3-term MMA sims + fragment top-2 ----------------
// block: 128 rows x 256 protos (2 passes of 128); 512 thr, 16 warps (wr 0..3 x wc 0..3)
// smem u32: sAh[128*68] | sAl | sBh[128*68] | sBl | sV1[128*4] | sV2 | sI1
#define C_AH 0
#define C_AL 8704
#define C_BH 17408
#define C_BL 26112
#define C_V1 34816
#define C_V2 35328
#define C_I1 35840
#define C_WORDS 36352                    // 145408 B

__global__ void __launch_bounds__(512, 1)
cluster_kernel(const float* __restrict__ emb, float* __restrict__ assignOut) {
    extern __shared__ float sm[];
    uint32_t* u = (uint32_t*)sm;

    const int tid  = threadIdx.x;
    const int lane = tid & 31;
    const int wid  = tid >> 5;        // 0..15
    const int wr   = wid >> 2;        // rows wr*32
    const int wc   = wid & 3;         // proto cols wc*32 (per pass)
    const int gq   = lane >> 2;
    const int tq   = lane & 3;
    const int base = blockIdx.x * 128;

    // stage emb hi/lo split: [r 128][m 64] pairs, stride CSS
    {
        uint32_t* sAh = u + C_AH;
        uint32_t* sAl = u + C_AL;
#pragma unroll
        for (int j = 0; j < 16; j++) {
            int f = tid + j * 512;
            int r = f >> 6, m = f & 63;
            float2 xv = *(const float2*)(emb + (size_t)(base + r) * HIDDEN + 2 * m);
            uint32_t lo, hi = h2_split2(xv.x, xv.y, lo);
            sAh[r * CSS + m] = hi;
            sAl[r * CSS + m] = lo;
        }
    }

    const uint32_t smb = smem_u32p(sm);
    const int arow  = wr * 32 + ((lane >> 3) & 1) * 8 + (lane & 7);
    const int akoff = ((lane >> 4) & 1) * 4;
    const uint32_t aH = smb + 4u * (C_AH + arow * CSS + akoff);
    const uint32_t aL = smb + 4u * (C_AL + arow * CSS + akoff);
    const int bcol  = wc * 32 + ((lane >> 4) & 1) * 8 + (lane & 7);
    const int bkoff = ((lane >> 3) & 1) * 4;
    const uint32_t bH = smb + 4u * (C_BH + bcol * CSS + bkoff);
    const uint32_t bL = smb + 4u * (C_BL + bcol * CSS + bkoff);

    float t1[4], t2[4];
    int   i1[4];
#pragma unroll
    for (int s = 0; s < 4; s++) { t1[s] = -3.4e38f; t2[s] = -3.4e38f; i1[s] = 0; }

    for (int pass = 0; pass < 2; pass++) {
        __syncthreads();
        {   // stage 128 protos (hi/lo) for this pass
            uint32_t* sBh = u + C_BH;
            uint32_t* sBl = u + C_BL;
            const uint4* ph = (const uint4*)(g_pnh + (size_t)(pass * 128) * 64);
            const uint4* pl = (const uint4*)(g_pnl + (size_t)(pass * 128) * 64);
#pragma unroll
            for (int j = 0; j < 4; j++) {
                int f = tid + j * 512;
                int n = f >> 4, m4 = f & 15;
                *(uint4*)(sBh + n * CSS + m4 * 4) = ph[f];
                *(uint4*)(sBl + n * CSS + m4 * 4) = pl[f];
            }
        }
        __syncthreads();

        float acc[2][4][4];
#pragma unroll
        for (int a = 0; a < 2; a++)
#pragma unroll
            for (int b = 0; b < 4; b++)
#pragma unroll
                for (int c = 0; c < 4; c++) acc[a][b][c] = 0.f;

#pragma unroll
        for (int ks = 0; ks < 8; ks++) {
            const uint32_t kso = (uint32_t)ks * 32u;   // ks*8 u32
            uint32_t bh[8], bl[8];
            LDSM_X4(bh + 0, bH + kso);                 // nf0, nf1 (hi)
            LDSM_X4(bh + 4, bH + 4352u + kso);         // nf2, nf3 (hi)  (+16 cols)
            LDSM_X4(bl + 0, bL + kso);
            LDSM_X4(bl + 4, bL + 4352u + kso);
#pragma unroll
            for (int mf = 0; mf < 2; mf++) {
                uint32_t ah[4], al[4];
                LDSM_X4(ah, aH + (uint32_t)mf * 4352u + kso);
                LDSM_X4(al, aL + (uint32_t)mf * 4352u + kso);
#pragma unroll
                for (int nf = 0; nf < 4; nf++) {
                    mma16(acc[mf][nf], ah, bh + nf * 2);
                    mma16(acc[mf][nf], ah, bl + nf * 2);
                    mma16(acc[mf][nf], al, bh + nf * 2);
                }
            }
        }

        // merge this pass's sims into per-thread top-2 (ascending proto index)
#pragma unroll
        for (int mf = 0; mf < 2; mf++)
#pragma unroll
            for (int rh = 0; rh < 2; rh++) {
                int s = mf * 2 + rh;
#pragma unroll
                for (int nf = 0; nf < 4; nf++) {
                    int idx0 = pass * 128 + wc * 32 + nf * 8 + tq * 2;
                    float v0 = acc[mf][nf][rh * 2 + 0];
                    float v1 = acc[mf][nf][rh * 2 + 1];
                    if (v0 > t1[s]) { t2[s] = t1[s]; t1[s] = v0; i1[s] = idx0; }
                    else if (v0 > t2[s]) t2[s] = v0;
                    if (v1 > t1[s]) { t2[s] = t1[s]; t1[s] = v1; i1[s] = idx0 + 1; }
                    else if (v1 > t2[s]) t2[s] = v1;
                }
            }
    }

    // reduce top-2 over the 4 tq lanes (width-4 groups), then across wc via smem
    float* sV1 = sm + C_V1;
    float* sV2 = sm + C_V2;
    int*   sI1 = (int*)sm + C_I1;
#pragma unroll
    for (int s = 0; s < 4; s++) {
        float a1 = t1[s], a2 = t2[s];
        int   ai = i1[s];
#pragma unroll
        for (int off = 2; off; off >>= 1) {
            float b1 = __shfl_down_sync(0xffffffffu, a1, off, 4);
            float b2 = __shfl_down_sync(0xffffffffu, a2, off, 4);
            int   bi = __shfl_down_sync(0xffffffffu, ai, off, 4);
            if (b1 > a1 || (b1 == a1 && bi < ai)) {
                a2 = fmaxf(a1, b2); a1 = b1; ai = bi;
            } else {
                a2 = fmaxf(a2, b1);
            }
        }
        if (tq == 0) {
            int row = wr * 32 + (s >> 1) * 16 + (s & 1) * 8 + gq;
            sV1[row * 4 + wc] = a1;
            sV2[row * 4 + wc] = a2;
            sI1[row * 4 + wc] = ai;
        }
    }
    __syncthreads();

    if (tid < 128) {
        float a1 = sV1[tid * 4], a2 = sV2[tid * 4];
        int   ai = sI1[tid * 4];
#pragma unroll
        for (int w = 1; w < 4; w++) {
            float b1 = sV1[tid * 4 + w], b2 = sV2[tid * 4 + w];
            int   bi = sI1[tid * 4 + w];
            if (b1 > a1 || (b1 == a1 && bi < ai)) {
                a2 = fmaxf(a1, b2); a1 = b1; ai = bi;
            } else {
                a2 = fmaxf(a2, b1);
            }
        }
        int row = base + tid;
        assignOut[row] = (float)ai;
        if (a1 - a2 < TAU) {
            int s = atomicAdd(&g_cnt, 1);
            g_list[s] = row;
        }
    }
}

// ---------------- fp32 fixup ----------------
__global__ void __launch_bounds__(256, 1)
fixup_kernel(const float* __restrict__ x,
             const float* __restrict__ Wf1, const float* __restrict__ Wf2,
             float* __restrict__ assignOut) {
    extern __shared__ float sm[];
    float* A  = sm;                 // 36864
    float* hb = sm + 36864;         // 4096
    float* ws = sm + 40960;         // 4096
    __shared__ int ridx[32];
    __shared__ float rv[8];
    __shared__ int   rp[8];

    const int tid = threadIdx.x;
    const int start = blockIdx.x * 32;
    const int cnt = g_cnt;
    if (start >= cnt) return;
    const int nr = min(32, cnt - start);
    if (tid < 32) {
        int srci = start + (tid < nr ? tid : nr - 1);
        ridx[tid] = g_list[srci];
    }
    __syncthreads();

    const float g0 = g_gp[0], invh = g_gp[1];
    const int tr = tid >> 5;
    const int tc = tid & 31;

    float acc[4][4];
    const float* Wf = Wf1;
    const float* src = x;
    bool gather = true;

    for (int layer = 0; layer < 2; layer++) {
        for (int e = tid; e < 32 * HIDDEN; e += 256) {
            int r = e >> 7, i = e & 127;
            float xv = gather ? src[(size_t)ridx[r] * HIDDEN + i] : src[r * HIDDEN + i];
            A[r * KDIM + i] = xv / (1.0f + __expf(-xv));
#pragma unroll
            for (int c = 0; c < NCOEF; c++)
                A[r * KDIM + HIDDEN + c * HIDDEN + i] = bspline_c(xv, c, g0, invh);
        }

#pragma unroll
        for (int a = 0; a < 4; a++)
#pragma unroll
            for (int b = 0; b < 4; b++) acc[a][b] = 0.f;

        for (int k0 = 0; k0 < KDIM; k0 += 32) {
            __syncthreads();
            const float4* gw = (const float4*)(Wf + (size_t)k0 * HIDDEN);
#pragma unroll
            for (int l = 0; l < 4; l++)
                ((float4*)ws)[tid + l * 256] = gw[tid + l * 256];
            __syncthreads();
#pragma unroll
            for (int kk = 0; kk < 32; kk++) {
                float a0 = A[(tr * 4 + 0) * KDIM + k0 + kk];
                float a1 = A[(tr * 4 + 1) * KDIM + k0 + kk];
                float a2 = A[(tr * 4 + 2) * KDIM + k0 + kk];
                float a3 = A[(tr * 4 + 3) * KDIM + k0 + kk];
                float4 w = ((float4*)ws)[kk * 32 + tc];
                acc[0][0] += a0 * w.x; acc[0][1] += a0 * w.y; acc[0][2] += a0 * w.z; acc[0][3] += a0 * w.w;
                acc[1][0] += a1 * w.x; acc[1][1] += a1 * w.y; acc[1][2] += a1 * w.z; acc[1][3] += a1 * w.w;
                acc[2][0] += a2 * w.x; acc[2][1] += a2 * w.y; acc[2][2] += a2 * w.z; acc[2][3] += a2 * w.w;
                acc[3][0] += a3 * w.x; acc[3][1] += a3 * w.y; acc[3][2] += a3 * w.z; acc[3][3] += a3 * w.w;
            }
        }
        __syncthreads();
#pragma unroll
        for (int ri = 0; ri < 4; ri++)
            ((float4*)(hb + (tr * 4 + ri) * HIDDEN))[tc] =
                make_float4(acc[ri][0], acc[ri][1], acc[ri][2], acc[ri][3]);
        __syncthreads();

        Wf = Wf2; src = hb; gather = false;
    }

    float sims[32];
#pragma unroll
    for (int r = 0; r < 32; r++) sims[r] = 0.f;
    for (int i = 0; i < HIDDEN; i++) {
        float pv = g_pnT[i * NPROTO + tid];
#pragma unroll
        for (int r = 0; r < 32; r++) sims[r] += hb[r * HIDDEN + i] * pv;
    }

    for (int r = 0; r < 32; r++) {
        float v = sims[r]; int bi = tid;
#pragma unroll
        for (int off = 16; off; off >>= 1) {
            float ov = __shfl_down_sync(0xffffffffu, v, off);
            int   oi = __shfl_down_sync(0xffffffffu, bi, off);
            if (ov > v || (ov == v && oi < bi)) { v = ov; bi = oi; }
        }
        if ((tid & 31) == 0) { rv[tid >> 5] = v; rp[tid >> 5] = bi; }
        __syncthreads();
        if (tid == 0) {
            float bv = rv[0]; int bb = rp[0];
#pragma unroll
            for (int w = 1; w < 8; w++)
                if (rv[w] > bv || (rv[w] == bv && rp[w] < bb)) { bv = rv[w]; bb = rp[w]; }
            if (r < nr) assignOut[ridx[r]] = (float)bb;
        }
        __syncthreads();
    }
}

// ---------------- launch ----------------
extern "C" void kernel_launch(void* const* d_in, const int* in_sizes, int n_in,
                              void* d_out, int out_size) {
    const float* x         = (const float*)d_in[0];
    const float* protos    = (const float*)d_in[1];
    const float* grid      = (const float*)d_in[2];
    const float* base_w1   = (const float*)d_in[3];
    const float* spline_w1 = (const float*)d_in[4];
    const float* scaler1   = (const float*)d_in[5];
    const float* base_w2   = (const float*)d_in[6];
    const float* spline_w2 = (const float*)d_in[7];
    const float* scaler2   = (const float*)d_in[8];

    int n = in_sizes[0] / HIDDEN;

    uint32_t *Wh1, *Wl1, *Wh2, *Wl2;
    float *Wf1, *Wf2, *h;
    cudaGetSymbolAddress((void**)&Wh1, g_Wh1);
    cudaGetSymbolAddress((void**)&Wl1, g_Wl1);
    cudaGetSymbolAddress((void**)&Wh2, g_Wh2);
    cudaGetSymbolAddress((void**)&Wl2, g_Wl2);
    cudaGetSymbolAddress((void**)&Wf1, g_Wf1);
    cudaGetSymbolAddress((void**)&Wf2, g_Wf2);
    cudaGetSymbolAddress((void**)&h,  g_h);

    prep_grid<<<1, 32>>>(grid);                                              // 0
    prep_weights<<<32, 256>>>(base_w1, spline_w1, scaler1, Wh1, Wl1, Wf1);   // 1
    prep_weights<<<32, 256>>>(base_w2, spline_w2, scaler2, Wh2, Wl2, Wf2);   // 2

    size_t smemL = SM_WORDS * 4;   // 149504 B
    cudaFuncSetAttribute(kan_tc, cudaFuncAttributeMaxDynamicSharedMemorySize, (int)smemL);

    float* emb = (float*)d_out;
    kan_tc<<<n / TILE_M, NTHR, smemL>>>(x, Wh1, Wl1, h);                     // 3  <- ncu capture
    kan_tc<<<n / TILE_M, NTHR, smemL>>>(h, Wh2, Wl2, emb);                   // 4

    if (out_size >= n * HIDDEN + n) {
        float* assign = emb + (size_t)n * HIDDEN;
        prep_protos<<<32, 256>>>(protos);                                    // 5
        reset_cnt<<<1, 32>>>();                                              // 6
        size_t smemC = C_WORDS * 4;                                          // 145408 B
        cudaFuncSetAttribute(cluster_kernel, cudaFuncAttributeMaxDynamicSharedMemorySize, (int)smemC);
        cluster_kernel<<<n / 128, 512, smemC>>>(emb, assign);                // 7
        size_t smemF = 45056 * sizeof(float);
        cudaFuncSetAttribute(fixup_kernel, cudaFuncAttributeMaxDynamicSharedMemorySize, (int)smemF);
        fixup_kernel<<<(n + 31) / 32, 256, smemF>>>(x, Wf1, Wf2, assign);    // 8
    }
}